// round 4
// baseline (speedup 1.0000x reference)
#include <cuda_runtime.h>

#define Nn   100000
#define Ee   1600000
#define TOTE 1700000   // E + N self loops
#define HIDD 128
#define NCLS 40
#define NEG_SLOPE 0.2f
#define BN_EPS 1e-5f

// ---------------- device scratch (static, no allocation) ----------------
__device__ float g_h[(size_t)Nn * HIDD];     // per-layer transformed features
__device__ float g_agg[(size_t)Nn * HIDD];   // aggregated / bn output
__device__ float g_es[Nn];
__device__ float g_ed[Nn];
__device__ float g_inv[Nn];
__device__ float g_w[TOTE];                  // unnormalized softmax weights (csr order)
__device__ int   g_srcs[TOTE];               // csr src ids
__device__ int   g_rowptr[Nn + 1];
__device__ int   g_deg[Nn];                  // degree, then reused as scatter cursor
__device__ float g_stats[4 * HIDD];          // sums/sqsums for the two BN passes
__device__ int   g_is64;                     // 1 if edge_index buffer holds int64

// ---------------- edge dtype detection ----------------
// int64 little-endian values < 2^31 have zero high words at odd int32 positions.
__global__ void k_detect(const int* __restrict__ ei32) {
    if (threadIdx.x == 0 && blockIdx.x == 0) {
        int allzero = 1;
        for (int k = 1; k < 64; k += 2)
            if (ei32[k] != 0) { allzero = 0; break; }
        g_is64 = allzero;
    }
}

__device__ __forceinline__ int load_idx(const void* ei, long long pos) {
    if (g_is64) return (int)((const long long*)ei)[pos];
    return ((const int*)ei)[pos];
}

// ---------------- CSR build ----------------
__global__ void k_zero() {
    int i = blockIdx.x * blockDim.x + threadIdx.x;
    if (i < Nn) g_deg[i] = 0;
    if (i < 4 * HIDD) g_stats[i] = 0.f;
}

__global__ void k_hist(const void* __restrict__ ei) {
    int e = blockIdx.x * blockDim.x + threadIdx.x;
    if (e >= TOTE) return;
    int dst = (e < Ee) ? load_idx(ei, (long long)Ee + e) : (e - Ee);
    if ((unsigned)dst >= Nn) return;
    atomicAdd(&g_deg[dst], 1);
}

__global__ void k_scan() {
    __shared__ int wsums[32];
    __shared__ int carry;
    int tid = threadIdx.x, lane = tid & 31, wp = tid >> 5;
    if (tid == 0) carry = 0;
    __syncthreads();
    for (int base = 0; base < Nn; base += 1024) {
        int i = base + tid;
        int v = (i < Nn) ? g_deg[i] : 0;
        int incl = v;
#pragma unroll
        for (int off = 1; off < 32; off <<= 1) {
            int t = __shfl_up_sync(0xffffffffu, incl, off);
            if (lane >= off) incl += t;
        }
        if (lane == 31) wsums[wp] = incl;
        __syncthreads();
        if (wp == 0) {
            int si = wsums[lane];
#pragma unroll
            for (int off = 1; off < 32; off <<= 1) {
                int t = __shfl_up_sync(0xffffffffu, si, off);
                if (lane >= off) si += t;
            }
            wsums[lane] = si;
        }
        __syncthreads();
        int wexcl = (wp > 0) ? wsums[wp - 1] : 0;
        if (i < Nn) g_rowptr[i] = carry + wexcl + incl - v;
        __syncthreads();
        if (tid == 0) carry += wsums[31];
        __syncthreads();
    }
    if (threadIdx.x == 0) g_rowptr[Nn] = carry;
}

__global__ void k_cursor() {
    int i = blockIdx.x * blockDim.x + threadIdx.x;
    if (i < Nn) g_deg[i] = g_rowptr[i];
}

__global__ void k_scatter(const void* __restrict__ ei) {
    int e = blockIdx.x * blockDim.x + threadIdx.x;
    if (e >= TOTE) return;
    int src, dst;
    if (e < Ee) {
        src = load_idx(ei, e);
        dst = load_idx(ei, (long long)Ee + e);
    } else {
        src = dst = e - Ee;
    }
    if ((unsigned)dst >= Nn || (unsigned)src >= Nn) return;
    int pos = atomicAdd(&g_deg[dst], 1);
    if ((unsigned)pos < TOTE) g_srcs[pos] = src;
}

// ---------------- GEMM [N,128] x [128,128] with fused attention scores ----------------
// block: 256 threads, 64 rows/block. thread (tx in [0,32), ty in [0,8)) -> 8 rows x 4 cols.
// K tiled in chunks of 32. Static smem: 24 KB.
__global__ void k_gemm128(const float* __restrict__ xin, int use_internal,
                          const float* __restrict__ W,
                          const float* __restrict__ as, const float* __restrict__ ad) {
    __shared__ __align__(16) float Xs[64 * 32];    // 8 KB
    __shared__ __align__(16) float Ws[32 * 128];   // 16 KB
    const float* X = use_internal ? g_agg : xin;

    int tid = threadIdx.x;
    int tx = tid & 31, ty = tid >> 5;
    int row0 = blockIdx.x * 64;

    float4 acc[8];
#pragma unroll
    for (int r = 0; r < 8; r++) acc[r] = make_float4(0.f, 0.f, 0.f, 0.f);

    const float4* W4 = (const float4*)W;
    const float4* X4 = (const float4*)X;
    float4* Ws4 = (float4*)Ws;
    float4* Xs4 = (float4*)Xs;

    for (int kc = 0; kc < 128; kc += 32) {
        for (int i = tid; i < 1024; i += 256)
            Ws4[i] = W4[(size_t)(kc + (i >> 5)) * 32 + (i & 31)];
        for (int i = tid; i < 512; i += 256) {
            int r = i >> 3, c = i & 7;
            float4 v = make_float4(0.f, 0.f, 0.f, 0.f);
            if (row0 + r < Nn) v = X4[(size_t)(row0 + r) * 32 + (kc >> 2) + c];
            Xs4[r * 8 + c] = v;
        }
        __syncthreads();

#pragma unroll 4
        for (int k = 0; k < 32; k++) {
            float4 wv = Ws4[k * 32 + tx];
#pragma unroll
            for (int r = 0; r < 8; r++) {
                float xv = Xs[(ty * 8 + r) * 32 + k];
                acc[r].x += xv * wv.x;
                acc[r].y += xv * wv.y;
                acc[r].z += xv * wv.z;
                acc[r].w += xv * wv.w;
            }
        }
        __syncthreads();
    }

    float4 as4 = ((const float4*)as)[tx];
    float4 ad4 = ((const float4*)ad)[tx];
    float4* H4 = (float4*)g_h;

#pragma unroll
    for (int r = 0; r < 8; r++) {
        int row = row0 + ty * 8 + r;
        if (row < Nn) {
            H4[(size_t)row * 32 + tx] = acc[r];
            float ps = acc[r].x * as4.x + acc[r].y * as4.y + acc[r].z * as4.z + acc[r].w * as4.w;
            float pd = acc[r].x * ad4.x + acc[r].y * ad4.y + acc[r].z * ad4.z + acc[r].w * ad4.w;
#pragma unroll
            for (int off = 16; off > 0; off >>= 1) {
                ps += __shfl_down_sync(0xffffffffu, ps, off);
                pd += __shfl_down_sync(0xffffffffu, pd, off);
            }
            if (tx == 0) { g_es[row] = ps; g_ed[row] = pd; }
        }
    }
}

// ---------------- segment softmax stats (thread per dst) ----------------
__global__ void k_smstats() {
    int i = blockIdx.x * blockDim.x + threadIdx.x;
    if (i >= Nn) return;
    int s = g_rowptr[i], e = g_rowptr[i + 1];
    float edi = g_ed[i];
    float mx = -1e30f;
    for (int j = s; j < e; j++) {
        float v = g_es[g_srcs[j]] + edi;
        v = (v > 0.f) ? v : NEG_SLOPE * v;
        mx = fmaxf(mx, v);
    }
    float sum = 0.f;
    for (int j = s; j < e; j++) {
        float v = g_es[g_srcs[j]] + edi;
        v = (v > 0.f) ? v : NEG_SLOPE * v;
        float w = __expf(v - mx);
        g_w[j] = w;
        sum += w;
    }
    g_inv[i] = (sum > 0.f) ? 1.f / sum : 0.f;
}

// ---------------- aggregation: warp per dst ----------------
__global__ void k_aggregate(const float* __restrict__ bias) {
    int gw = (blockIdx.x * blockDim.x + threadIdx.x) >> 5;
    int lane = threadIdx.x & 31;
    if (gw >= Nn) return;
    int s = g_rowptr[gw], e = g_rowptr[gw + 1];
    const float4* H4 = (const float4*)g_h;
    float4 acc = make_float4(0.f, 0.f, 0.f, 0.f);
    int j = s;
    for (; j + 1 < e; j += 2) {
        float a0 = g_w[j], a1 = g_w[j + 1];
        int s0 = g_srcs[j], s1 = g_srcs[j + 1];
        float4 v0 = H4[(size_t)s0 * 32 + lane];
        float4 v1 = H4[(size_t)s1 * 32 + lane];
        acc.x += a0 * v0.x + a1 * v1.x;
        acc.y += a0 * v0.y + a1 * v1.y;
        acc.z += a0 * v0.z + a1 * v1.z;
        acc.w += a0 * v0.w + a1 * v1.w;
    }
    if (j < e) {
        float a0 = g_w[j];
        int s0 = g_srcs[j];
        float4 v0 = H4[(size_t)s0 * 32 + lane];
        acc.x += a0 * v0.x; acc.y += a0 * v0.y;
        acc.z += a0 * v0.z; acc.w += a0 * v0.w;
    }
    float inv = g_inv[gw];
    float4 b4 = ((const float4*)bias)[lane];
    float4 o;
    o.x = acc.x * inv + b4.x;
    o.y = acc.y * inv + b4.y;
    o.z = acc.z * inv + b4.z;
    o.w = acc.w * inv + b4.w;
    ((float4*)g_agg)[(size_t)gw * 32 + lane] = o;
}

// ---------------- BN stats ----------------
__global__ void k_bnreduce(int which) {
    __shared__ float sh[512], sh2[512];
    int t = threadIdx.x;
    int c = t & 127;
    int row0 = blockIdx.x * 512;
    int rend = min(row0 + 512, Nn);
    float s = 0.f, s2 = 0.f;
    for (int r = row0 + (t >> 7); r < rend; r += 4) {
        float v = g_agg[(size_t)r * 128 + c];
        s += v; s2 += v * v;
    }
    sh[t] = s; sh2[t] = s2;
    __syncthreads();
    if (t < 128) {
        float a  = sh[t]  + sh[t + 128]  + sh[t + 256]  + sh[t + 384];
        float a2 = sh2[t] + sh2[t + 128] + sh2[t + 256] + sh2[t + 384];
        atomicAdd(&g_stats[which * 256 + t], a);
        atomicAdd(&g_stats[which * 256 + 128 + t], a2);
    }
}

// ---------------- BN normalize + ELU (in place on g_agg) ----------------
__global__ void k_bnelu(const float* __restrict__ gamma, const float* __restrict__ beta, int which) {
    __shared__ float ssc[128], ssh[128];
    int t = threadIdx.x;
    if (t < 128) {
        float mu  = g_stats[which * 256 + t] * (1.f / Nn);
        float var = g_stats[which * 256 + 128 + t] * (1.f / Nn) - mu * mu;
        float sc = gamma[t] * rsqrtf(var + BN_EPS);
        ssc[t] = sc;
        ssh[t] = beta[t] - mu * sc;
    }
    __syncthreads();
    float4* Z4 = (float4*)g_agg;
    const int total = Nn * 32;
    for (int idx = blockIdx.x * blockDim.x + t; idx < total; idx += gridDim.x * blockDim.x) {
        float4 v = Z4[idx];
        int cb = (idx & 31) * 4;
        float x0 = v.x * ssc[cb + 0] + ssh[cb + 0];
        float x1 = v.y * ssc[cb + 1] + ssh[cb + 1];
        float x2 = v.z * ssc[cb + 2] + ssh[cb + 2];
        float x3 = v.w * ssc[cb + 3] + ssh[cb + 3];
        v.x = (x0 > 0.f) ? x0 : (__expf(x0) - 1.f);
        v.y = (x1 > 0.f) ? x1 : (__expf(x1) - 1.f);
        v.z = (x2 > 0.f) ? x2 : (__expf(x2) - 1.f);
        v.w = (x3 > 0.f) ? x3 : (__expf(x3) - 1.f);
        Z4[idx] = v;
    }
}

// ---------------- output GEMM [N,128] x [128,40] ----------------
__global__ void k_gemm_out(const float* __restrict__ Wo, const float* __restrict__ bo,
                           float* __restrict__ out) {
    __shared__ __align__(16) float Xs[32 * 129];
    __shared__ __align__(16) float Ws[128 * 40];
    int tid = threadIdx.x;
    int row0 = blockIdx.x * 32;

    for (int i = tid; i < 128 * 40; i += 320) Ws[i] = Wo[i];
    for (int i = tid; i < 32 * 128; i += 320) {
        int r = i >> 7, c = i & 127;
        Xs[r * 129 + c] = (row0 + r < Nn) ? g_agg[(size_t)(row0 + r) * 128 + c] : 0.f;
    }
    __syncthreads();

    int r = tid & 31;
    int c4 = tid >> 5;
    float4 acc = make_float4(0.f, 0.f, 0.f, 0.f);
#pragma unroll 4
    for (int k = 0; k < 128; k++) {
        float xv = Xs[r * 129 + k];
        float wx = Ws[k * 40 + c4 * 4 + 0];
        float wy = Ws[k * 40 + c4 * 4 + 1];
        float wz = Ws[k * 40 + c4 * 4 + 2];
        float ww = Ws[k * 40 + c4 * 4 + 3];
        acc.x += xv * wx;
        acc.y += xv * wy;
        acc.z += xv * wz;
        acc.w += xv * ww;
    }
    int row = row0 + r;
    if (row < Nn) {
        float4 b4 = ((const float4*)bo)[c4];
        acc.x += b4.x; acc.y += b4.y; acc.z += b4.z; acc.w += b4.w;
        ((float4*)out)[(size_t)row * 10 + c4] = acc;
    }
}

// ---------------- launch ----------------
extern "C" void kernel_launch(void* const* d_in, const int* in_sizes, int n_in,
                              void* d_out, int out_size) {
    const float* x    = (const float*)d_in[0];
    const void*  ei   = d_in[1];
    const float* W1   = (const float*)d_in[2];
    const float* as1  = (const float*)d_in[3];
    const float* ad1  = (const float*)d_in[4];
    const float* b1   = (const float*)d_in[5];
    const float* W2   = (const float*)d_in[6];
    const float* as2  = (const float*)d_in[7];
    const float* ad2  = (const float*)d_in[8];
    const float* b2   = (const float*)d_in[9];
    const float* gamma= (const float*)d_in[10];
    const float* beta = (const float*)d_in[11];
    const float* Wout = (const float*)d_in[12];
    const float* bout = (const float*)d_in[13];
    float* out = (float*)d_out;

    const int ZB = (Nn + 255) / 256;          // 391
    const int EB = (TOTE + 255) / 256;        // 6641
    const int GB = (Nn + 63) / 64;            // 1563
    const int OB = (Nn + 31) / 32;            // 3125
    const int AB = (Nn * 32 + 255) / 256;     // 12500
    const int RB = (Nn + 511) / 512;          // 196

    // CSR build
    k_detect<<<1, 32>>>((const int*)ei);
    k_zero<<<ZB, 256>>>();
    k_hist<<<EB, 256>>>(ei);
    k_scan<<<1, 1024>>>();
    k_cursor<<<ZB, 256>>>();
    k_scatter<<<EB, 256>>>(ei);

    // layer 1
    k_gemm128<<<GB, 256>>>(x, 0, W1, as1, ad1);
    k_smstats<<<ZB, 256>>>();
    k_aggregate<<<AB, 256>>>(b1);
    k_bnreduce<<<RB, 512>>>(0);
    k_bnelu<<<2048, 256>>>(gamma, beta, 0);

    // layer 2
    k_gemm128<<<GB, 256>>>(x, 1, W2, as2, ad2);
    k_smstats<<<ZB, 256>>>();
    k_aggregate<<<AB, 256>>>(b2);
    k_bnreduce<<<RB, 512>>>(1);
    k_bnelu<<<2048, 256>>>(gamma, beta, 1);

    // output head
    k_gemm_out<<<OB, 320>>>(Wout, bout, out);
}